// round 5
// baseline (speedup 1.0000x reference)
#include <cuda_runtime.h>

// ---------------------------------------------------------------------------
// MotionPrediction: fused 3-layer cyclic-expert MLP
//   out = L3( relu(L2( relu(L1(X)) )) ),  L(x) = sum_e c_e(row) * (x @ W_e + b_e)
// Implemented as per-layer GEMM  A_aug[128,1024] @ Wcat[1024,256] per CTA tile,
// with the per-(row,expert) coefficient folded into the A-fragment load.
// tf32 mma.sync (m16n8k8), RN rounding on both operands.
// ---------------------------------------------------------------------------

#define BATCH     65536
#define D         256
#define BM        128            // rows per CTA
#define HS_STRIDE 260            // Hs row stride (floats): bank = 4g+c -> conflict-free A frags
#define WS_STRIDE 264            // Ws row stride (floats): bank = 8k+g -> conflict-free B frags
#define KT        16             // K rows per cp.async stage
#define WS_TILEF  (KT * WS_STRIDE)      // 4224 floats per stage
#define NSTAGE    4
#define NTILES    64             // 1024 / KT  tiles per layer
#define CES_STRIDE 132

#define SMEM_FLOATS (BM*HS_STRIDE + NSTAGE*WS_TILEF + 4*CES_STRIDE + 4*WS_STRIDE)
// = 33280 + 16896 + 528 + 1056 = 51760 floats = 207040 bytes

// tf32-rounded weights, [3 layers][4 experts][256 in][256 out]
__device__ float g_Wr[3 * 4 * 256 * 256];

__device__ __forceinline__ unsigned f2tf(float f) {
    unsigned u;
    asm("cvt.rna.tf32.f32 %0, %1;" : "=r"(u) : "f"(f));
    return u;
}

__device__ __forceinline__ void mma8(float* c, const unsigned* a, unsigned b0, unsigned b1) {
    asm volatile(
        "mma.sync.aligned.m16n8k8.row.col.f32.tf32.tf32.f32 "
        "{%0,%1,%2,%3}, {%4,%5,%6,%7}, {%8,%9}, {%0,%1,%2,%3};\n"
        : "+f"(c[0]), "+f"(c[1]), "+f"(c[2]), "+f"(c[3])
        : "r"(a[0]), "r"(a[1]), "r"(a[2]), "r"(a[3]), "r"(b0), "r"(b1));
}

__global__ void prep_round(const float* __restrict__ W1,
                           const float* __restrict__ W2,
                           const float* __restrict__ W3) {
    int i = blockIdx.x * 256 + threadIdx.x;   // grid 1024 -> 262144 indices
    g_Wr[i]          = __uint_as_float(f2tf(W1[i]));
    g_Wr[i + 262144] = __uint_as_float(f2tf(W2[i]));
    g_Wr[i + 524288] = __uint_as_float(f2tf(W3[i]));
}

// stage one [KT x 256] weight tile into smem stage buffer (padded stride)
__device__ __forceinline__ void cp_tile(const float* __restrict__ Wl, int t,
                                        unsigned dst_u32, int tid) {
    const float* src = Wl + (size_t)t * (KT * D);
#pragma unroll
    for (int i = 0; i < 4; i++) {                 // KT*64 f4 = 1024 ; 256 thr -> 4 each
        int f4 = tid + i * 256;
        int r  = f4 >> 6, c4 = f4 & 63;
        unsigned d = dst_u32 + (unsigned)((r * WS_STRIDE + c4 * 4) * 4);
        const float* s = src + r * D + c4 * 4;
        asm volatile("cp.async.cg.shared.global [%0], [%1], 16;\n" :: "r"(d), "l"(s));
    }
}

__global__ __launch_bounds__(256, 1)
void fused_kernel(const float* __restrict__ X, const float* __restrict__ phi,
                  const float* __restrict__ b1, const float* __restrict__ b2,
                  const float* __restrict__ b3, float* __restrict__ out) {
    extern __shared__ float sm[];
    float* Hs  = sm;                          // [128][260]
    float* Ws  = Hs + BM * HS_STRIDE;         // [4][16][264]
    float* ces = Ws + NSTAGE * WS_TILEF;      // [4 experts][132]
    float* bs  = ces + 4 * CES_STRIDE;        // [4 experts][264]

    const int tid  = threadIdx.x;
    const int lane = tid & 31;
    const int wid  = tid >> 5;
    const int wm   = wid & 1;                 // 2 row-blocks of 64
    const int wn   = wid >> 1;                // 4 col-blocks of 64
    const int g    = lane >> 2;
    const int c    = lane & 3;
    const int row0 = blockIdx.x * BM;

    const unsigned ws_u32 = (unsigned)__cvta_generic_to_shared(Ws);

    // ---- per-row cubic mixing coefficients (bit-exact with reference) ----
    if (tid < BM) {
        float w  = phi[row0 + tid] * 0.63661977236758134308f;  // 2/pi, fp32 RN
        float w2 = w * w;
        float w3 = w2 * w;
        float cf0 = -0.5f * w + w2 - 0.5f * w3;
        float cf1 = -2.5f * w2 + 1.5f * w3;
        float cf2 = 0.5f * w + 2.0f * w2 - 1.5f * w3;
        float cf3 = -0.5f * w2 + 0.5f * w3;
        int wi = ((int)w) & 3;
        ces[((wi + 3) & 3) * CES_STRIDE + tid] = cf0;   // expert (wi-1)%4
        ces[( wi          ) * CES_STRIDE + tid] = cf1;   // expert wi
        ces[((wi + 1) & 3) * CES_STRIDE + tid] = cf2;   // expert (wi+1)%4
        ces[((wi + 2) & 3) * CES_STRIDE + tid] = cf3;   // expert (wi+2)%4
    }

    // ---- load X tile into Hs (fp32) ----
#pragma unroll
    for (int i = 0; i < 8; i++) {
        int f4 = tid + i * 256;               // 128*64 f4 = 8192 -> 32 each... (8 per thr*... 8 iters)
        int r  = f4 >> 6, c4 = f4 & 63;
        float4 v = *reinterpret_cast<const float4*>(X + (size_t)(row0 + r) * D + c4 * 4);
        *reinterpret_cast<float4*>(Hs + r * HS_STRIDE + c4 * 4) = v;
    }
    // NOTE: 8192 f4 / 256 thr = 32 each -> need 32 iterations, fix below
#pragma unroll
    for (int i = 8; i < 32; i++) {
        int f4 = tid + i * 256;
        int r  = f4 >> 6, c4 = f4 & 63;
        float4 v = *reinterpret_cast<const float4*>(X + (size_t)(row0 + r) * D + c4 * 4);
        *reinterpret_cast<float4*>(Hs + r * HS_STRIDE + c4 * 4) = v;
    }

    float C[4][8][4];

    for (int layer = 0; layer < 3; layer++) {
        const float* Wl = g_Wr + layer * 262144;
        const float* bl = (layer == 0) ? b1 : (layer == 1) ? b2 : b3;

        // bias rows into bs[e][0..255]
        for (int i = tid; i < 1024; i += 256) {
            int e = i >> 8, n = i & 255;
            bs[e * WS_STRIDE + n] = bl[i];
        }

#pragma unroll
        for (int mi = 0; mi < 4; mi++)
#pragma unroll
            for (int nf = 0; nf < 8; nf++)
#pragma unroll
                for (int q = 0; q < 4; q++) C[mi][nf][q] = 0.0f;

        // ---- prologue: stage tiles 0..2 ----
#pragma unroll
        for (int p = 0; p < 3; p++) {
            cp_tile(Wl, p, ws_u32 + (unsigned)((p & 3) * WS_TILEF * 4), tid);
            asm volatile("cp.async.commit_group;\n" ::: "memory");
        }

        float ce8[8];
        int cur_e = -1;

        for (int t = 0; t < NTILES; t++) {
            // wait until tile t's group is complete
            if (t <= NTILES - 3)      { asm volatile("cp.async.wait_group 2;\n" ::: "memory"); }
            else if (t == NTILES - 2) { asm volatile("cp.async.wait_group 1;\n" ::: "memory"); }
            else                      { asm volatile("cp.async.wait_group 0;\n" ::: "memory"); }
            __syncthreads();

            if (t + 3 < NTILES) {
                cp_tile(Wl, t + 3, ws_u32 + (unsigned)(((t + 3) & 3) * WS_TILEF * 4), tid);
                asm volatile("cp.async.commit_group;\n" ::: "memory");
            }

            const int e = t >> 4;             // 16 tiles per expert
            if (e != cur_e) {
                cur_e = e;
#pragma unroll
                for (int mi = 0; mi < 4; mi++) {
                    int r = wm * 64 + mi * 16 + g;
                    ce8[mi * 2]     = ces[e * CES_STRIDE + r];
                    ce8[mi * 2 + 1] = ces[e * CES_STRIDE + r + 8];
                }
            }
            const float* buf = Ws + (t & 3) * WS_TILEF;
            const int kc0 = (t & 15) * KT;    // column offset within this expert's 256

#pragma unroll
            for (int k8 = 0; k8 < KT / 8; k8++) {
                const int kc = kc0 + k8 * 8 + c;
                unsigned a[4][4];
#pragma unroll
                for (int mi = 0; mi < 4; mi++) {
                    int r = wm * 64 + mi * 16 + g;
                    a[mi][0] = f2tf(Hs[r * HS_STRIDE + kc]           * ce8[mi * 2]);
                    a[mi][1] = f2tf(Hs[(r + 8) * HS_STRIDE + kc]     * ce8[mi * 2 + 1]);
                    a[mi][2] = f2tf(Hs[r * HS_STRIDE + kc + 4]       * ce8[mi * 2]);
                    a[mi][3] = f2tf(Hs[(r + 8) * HS_STRIDE + kc + 4] * ce8[mi * 2 + 1]);
                }
#pragma unroll
                for (int nf = 0; nf < 8; nf++) {
                    int n = wn * 64 + nf * 8 + g;
                    unsigned bb0 = __float_as_uint(buf[(k8 * 8 + c)     * WS_STRIDE + n]);
                    unsigned bb1 = __float_as_uint(buf[(k8 * 8 + c + 4) * WS_STRIDE + n]);
#pragma unroll
                    for (int mi = 0; mi < 4; mi++) mma8(C[mi][nf], a[mi], bb0, bb1);
                }
            }
        }
        __syncthreads();   // all Hs reads of this layer complete

        // ---- bias as one K=8 mma: A cols = experts (0..3), pad cols 4..7 = 0 ----
        {
            unsigned a[4][4];
#pragma unroll
            for (int mi = 0; mi < 4; mi++) {
                int r = wm * 64 + mi * 16 + g;
                a[mi][0] = f2tf(ces[c * CES_STRIDE + r]);
                a[mi][1] = f2tf(ces[c * CES_STRIDE + r + 8]);
                a[mi][2] = 0u;
                a[mi][3] = 0u;
            }
#pragma unroll
            for (int nf = 0; nf < 8; nf++) {
                int n = wn * 64 + nf * 8 + g;
                unsigned bb0 = __float_as_uint(bs[c * WS_STRIDE + n]);
#pragma unroll
                for (int mi = 0; mi < 4; mi++) mma8(C[mi][nf], a[mi], bb0, 0u);
            }
        }

        // ---- epilogue ----
        if (layer < 2) {
#pragma unroll
            for (int mi = 0; mi < 4; mi++) {
                int r = wm * 64 + mi * 16 + g;
#pragma unroll
                for (int nf = 0; nf < 8; nf++) {
                    int coln = wn * 64 + nf * 8 + 2 * c;
                    float2 v0 = make_float2(fmaxf(C[mi][nf][0], 0.0f), fmaxf(C[mi][nf][1], 0.0f));
                    float2 v1 = make_float2(fmaxf(C[mi][nf][2], 0.0f), fmaxf(C[mi][nf][3], 0.0f));
                    *reinterpret_cast<float2*>(Hs + r * HS_STRIDE + coln)       = v0;
                    *reinterpret_cast<float2*>(Hs + (r + 8) * HS_STRIDE + coln) = v1;
                }
            }
            __syncthreads();
        } else {
#pragma unroll
            for (int mi = 0; mi < 4; mi++) {
                int r = wm * 64 + mi * 16 + g;
#pragma unroll
                for (int nf = 0; nf < 8; nf++) {
                    int coln = wn * 64 + nf * 8 + 2 * c;
                    *reinterpret_cast<float2*>(out + (size_t)(row0 + r) * D + coln) =
                        make_float2(C[mi][nf][0], C[mi][nf][1]);
                    *reinterpret_cast<float2*>(out + (size_t)(row0 + r + 8) * D + coln) =
                        make_float2(C[mi][nf][2], C[mi][nf][3]);
                }
            }
        }
    }
}

extern "C" void kernel_launch(void* const* d_in, const int* in_sizes, int n_in,
                              void* d_out, int out_size) {
    const float* X   = (const float*)d_in[0];
    const float* phi = (const float*)d_in[1];
    const float* W1  = (const float*)d_in[2];
    const float* b1  = (const float*)d_in[3];
    const float* W2  = (const float*)d_in[4];
    const float* b2  = (const float*)d_in[5];
    const float* W3  = (const float*)d_in[6];
    const float* b3  = (const float*)d_in[7];
    float* out = (float*)d_out;

    size_t smem = (size_t)SMEM_FLOATS * sizeof(float);   // 207040 B
    cudaFuncSetAttribute(fused_kernel, cudaFuncAttributeMaxDynamicSharedMemorySize, (int)smem);

    prep_round<<<1024, 256>>>(W1, W2, W3);
    fused_kernel<<<BATCH / BM, 256, smem>>>(X, phi, b1, b2, b3, out);
}